// round 9
// baseline (speedup 1.0000x reference)
#include <cuda_runtime.h>
#include <math.h>
#include <stdint.h>

#define IMG_H 240
#define IMG_W 320
#define NV 12288
#define NF 4096
#define NCH 11
#define TSZ 16
#define CHF 128   // faces per smem chunk

// ---------------- device scratch (no allocations allowed) ----------------
__device__ float g_vn[NV * 3];                 // vertex normal accumulators
__device__ float g_px[NV], g_py[NV], g_pz[NV]; // screen coords + ndc z
__device__ float g_iw[NV], g_wcl[NV];          // inv_w and clip w
__device__ float g_vcol[NV * NCH];             // per-vertex 11-ch color

struct __align__(16) FaceRec {
    float bx, by, cx, cy;
    float d0x, d0y, d1x, d1y;    // d0=(cy-by, cx-bx), d1=(ay-cy, ax-cx)
    float inv_area, z0, z1, z2;
    float iw0, iw1, iw2, pad;
};
struct __align__(16) FaceBB { float x0, x1, y0, y1; };

__device__ FaceRec g_face[NF];
__device__ FaceBB  g_bb[NF];
__device__ float   g_fcol[NF * 3 * NCH];

struct Proj { float m[16]; };   // proj matrix (numpy layout, pre-transpose)

// ---------------- kernels ----------------
__global__ void k_zero_vn() {
    int i = blockIdx.x * blockDim.x + threadIdx.x;
    if (i < NV * 3) g_vn[i] = 0.0f;
}

__global__ void k_facenorm(const float* __restrict__ verts,
                           const int* __restrict__ faces) {
    int f = blockIdx.x * blockDim.x + threadIdx.x;
    if (f >= NF) return;
    int i0 = faces[3 * f + 0], i1 = faces[3 * f + 1], i2 = faces[3 * f + 2];
    float ax = verts[3 * i0], ay = verts[3 * i0 + 1], az = verts[3 * i0 + 2];
    float bx = verts[3 * i1], by = verts[3 * i1 + 1], bz = verts[3 * i1 + 2];
    float cx = verts[3 * i2], cy = verts[3 * i2 + 1], cz = verts[3 * i2 + 2];
    float e1x = bx - ax, e1y = by - ay, e1z = bz - az;
    float e2x = cx - ax, e2y = cy - ay, e2z = cz - az;
    float nx = e1y * e2z - e1z * e2y;
    float ny = e1z * e2x - e1x * e2z;
    float nz = e1x * e2y - e1y * e2x;
    float nrm = sqrtf(nx * nx + ny * ny + nz * nz);
    nrm = fmaxf(nrm, 1e-12f);
    nx /= nrm; ny /= nrm; nz /= nrm;
    atomicAdd(&g_vn[3 * i0 + 0], nx); atomicAdd(&g_vn[3 * i0 + 1], ny); atomicAdd(&g_vn[3 * i0 + 2], nz);
    atomicAdd(&g_vn[3 * i1 + 0], nx); atomicAdd(&g_vn[3 * i1 + 1], ny); atomicAdd(&g_vn[3 * i1 + 2], nz);
    atomicAdd(&g_vn[3 * i2 + 0], nx); atomicAdd(&g_vn[3 * i2 + 1], ny); atomicAdd(&g_vn[3 * i2 + 2], nz);
}

__global__ void k_vertex(const float* __restrict__ verts,
                         const float* __restrict__ pose, Proj P) {
    int v = blockIdx.x * blockDim.x + threadIdx.x;
    if (v >= NV) return;
    float x = verts[3 * v], y = verts[3 * v + 1], z = verts[3 * v + 2];
    float p[16];
    #pragma unroll
    for (int i = 0; i < 16; i++) p[i] = pose[i];

    // vert_3d = pose_rot @ v + t
    float wx = p[0] * x + p[1] * y + p[2]  * z + p[3];
    float wy = p[4] * x + p[5] * y + p[6]  * z + p[7];
    float wz = p[8] * x + p[9] * y + p[10] * z + p[11];
    // cam = cam_pose @ [v,1];  cam_pose rows: (row0, -row1, -row2, row3)
    float cam[4];
    cam[0] = wx;
    cam[1] = -wy;
    cam[2] = -wz;
    cam[3] = p[12] * x + p[13] * y + p[14] * z + p[15];
    // clip_j = sum_k proj_np[j][k] * cam_k
    float clip[4];
    #pragma unroll
    for (int j = 0; j < 4; j++) {
        clip[j] = P.m[4 * j + 0] * cam[0] + P.m[4 * j + 1] * cam[1]
                + P.m[4 * j + 2] * cam[2] + P.m[4 * j + 3] * cam[3];
    }
    float wc = clip[3];
    float denw = (fabsf(wc) > 1e-9f) ? wc : 1e-9f;
    float iw = 1.0f / denw;
    float n0 = clip[0] * iw, n1 = clip[1] * iw, n2 = clip[2] * iw;
    g_px[v]  = (n0 + 1.0f) * 0.5f * (float)IMG_W;
    g_py[v]  = (1.0f - n1) * 0.5f * (float)IMG_H;
    g_pz[v]  = n2;
    g_iw[v]  = iw;
    g_wcl[v] = wc;

    // normalize accumulated vertex normal
    float vx = g_vn[3 * v], vy = g_vn[3 * v + 1], vz = g_vn[3 * v + 2];
    float nn = sqrtf(vx * vx + vy * vy + vz * vz);
    nn = fmaxf(nn, 1e-12f);
    vx /= nn; vy /= nn; vz /= nn;

    float* col = &g_vcol[v * NCH];
    col[0] = 1.0f;
    col[1] = wx; col[2] = wy; col[3] = wz;
    col[4] = vx; col[5] = vy; col[6] = vz;
    col[7] = x;  col[8] = y;  col[9] = z; col[10] = 1.0f;
}

__global__ void k_facesetup(const int* __restrict__ faces) {
    int f = blockIdx.x * blockDim.x + threadIdx.x;
    if (f >= NF) return;
    int i0 = faces[3 * f + 0], i1 = faces[3 * f + 1], i2 = faces[3 * f + 2];
    float ax = g_px[i0], ay = g_py[i0];
    float bx = g_px[i1], by = g_py[i1];
    float cx = g_px[i2], cy = g_py[i2];
    bool wok = (g_wcl[i0] > 1e-6f) && (g_wcl[i1] > 1e-6f) && (g_wcl[i2] > 1e-6f);
    float area = (bx - ax) * (cy - ay) - (by - ay) * (cx - ax);
    bool areaok = fabsf(area) > 1e-12f;
    float inv_area = 1.0f / (areaok ? area : 1e-12f);
    bool valid = areaok && wok;

    FaceRec r;
    r.bx = bx; r.by = by; r.cx = cx; r.cy = cy;
    r.d0x = cy - by; r.d0y = cx - bx;
    r.d1x = ay - cy; r.d1y = ax - cx;
    r.inv_area = valid ? inv_area : 0.0f;
    r.z0 = valid ? g_pz[i0] : 3e9f;
    r.z1 = valid ? g_pz[i1] : 3e9f;
    r.z2 = valid ? g_pz[i2] : 3e9f;
    r.iw0 = g_iw[i0]; r.iw1 = g_iw[i1]; r.iw2 = g_iw[i2];
    r.pad = 0.0f;
    g_face[f] = r;

    // The reference's e0/e1 satisfy e0 = -wA, e1 = -wB, e2 = 2 - wC
    // (true barycentrics w). The drawn region {e0>=0, e1>=0, e2>=0} is the
    // triangle REFLECTED through vertex C: vertices {C, 2C-A, 2C-B}.
    FaceBB bb;
    if (valid) {
        float rax = 2.0f * cx - ax, ray = 2.0f * cy - ay;   // 2C - A
        float rbx = 2.0f * cx - bx, rby = 2.0f * cy - by;   // 2C - B
        bb.x0 = fminf(cx, fminf(rax, rbx)) - 0.5f;
        bb.x1 = fmaxf(cx, fmaxf(rax, rbx)) + 0.5f;
        bb.y0 = fminf(cy, fminf(ray, rby)) - 0.5f;
        bb.y1 = fmaxf(cy, fmaxf(ray, rby)) + 0.5f;
    } else {
        bb.x0 = 1e30f; bb.x1 = -1e30f; bb.y0 = 1e30f; bb.y1 = -1e30f;
    }
    g_bb[f] = bb;

    float* fc = &g_fcol[f * 3 * NCH];
    const float* c0p = &g_vcol[i0 * NCH];
    const float* c1p = &g_vcol[i1 * NCH];
    const float* c2p = &g_vcol[i2 * NCH];
    #pragma unroll
    for (int c = 0; c < NCH; c++) { fc[c] = c0p[c]; fc[NCH + c] = c1p[c]; fc[2 * NCH + c] = c2p[c]; }
}

__global__ __launch_bounds__(TSZ * TSZ) void k_raster(float* __restrict__ out) {
    __shared__ FaceRec sf[CHF];
    __shared__ FaceBB  sb[CHF];

    int tx = threadIdx.x, ty = threadIdx.y;
    int x = blockIdx.x * TSZ + tx;
    int y = blockIdx.y * TSZ + ty;
    float X = (float)x + 0.5f, Y = (float)y + 0.5f;
    float tX0 = (float)(blockIdx.x * TSZ) + 0.5f, tX1 = tX0 + (float)(TSZ - 1);
    float tY0 = (float)(blockIdx.y * TSZ) + 0.5f, tY1 = tY0 + (float)(TSZ - 1);
    int tid = ty * TSZ + tx;

    float best = 1e9f;
    int bf = -1;

    for (int base = 0; base < NF; base += CHF) {
        const float4* src = (const float4*)&g_face[base];
        float4* dst = (float4*)sf;
        #pragma unroll
        for (int i = 0; i < (CHF * 4) / (TSZ * TSZ); i++)
            dst[tid + i * TSZ * TSZ] = src[tid + i * TSZ * TSZ];
        if (tid < CHF) ((float4*)sb)[tid] = ((const float4*)&g_bb[base])[tid];
        __syncthreads();

        for (int j = 0; j < CHF; j++) {
            FaceBB bb = sb[j];
            // tile-uniform cull: same outcome for every thread in the block
            if (bb.x1 < tX0 || bb.x0 > tX1 || bb.y1 < tY0 || bb.y0 > tY1) continue;
            const FaceRec& f = sf[j];
            float e0 = ((X - f.bx) * f.d0x - (Y - f.by) * f.d0y) * f.inv_area;
            float e1 = ((X - f.cx) * f.d1x - (Y - f.cy) * f.d1y) * f.inv_area;
            float e2 = 1.0f - e0 - e1;
            float depth = e0 * f.z0 + e1 * f.z1 + e2 * f.z2;
            bool inside = (e0 >= 0.0f) & (e1 >= 0.0f) & (e2 >= 0.0f)
                        & (depth >= -1.0f) & (depth <= 1.0f);
            if (inside && depth < best) { best = depth; bf = base + j; }
        }
        __syncthreads();
    }

    float col[NCH];
    if (bf >= 0) {
        FaceRec f = g_face[bf];
        float e0 = ((X - f.bx) * f.d0x - (Y - f.by) * f.d0y) * f.inv_area;
        float e1 = ((X - f.cx) * f.d1x - (Y - f.cy) * f.d1y) * f.inv_area;
        float e2 = 1.0f - e0 - e1;
        float p0 = e0 * f.iw0, p1 = e1 * f.iw1, p2 = e2 * f.iw2;
        float den = p0 + p1 + p2;
        den = (fabsf(den) > 1e-12f) ? den : 1e-12f;
        float w0 = p0 / den, w1 = p1 / den, w2 = p2 / den;
        const float* fc = &g_fcol[bf * 3 * NCH];
        #pragma unroll
        for (int c = 0; c < NCH; c++)
            col[c] = w0 * fc[c] + w1 * fc[NCH + c] + w2 * fc[2 * NCH + c];
    } else {
        #pragma unroll
        for (int c = 0; c < NCH; c++) col[c] = 0.0f;
    }
    float* o = out + ((size_t)y * IMG_W + x) * NCH;
    #pragma unroll
    for (int c = 0; c < NCH; c++) o[c] = col[c];
}

// ---------------- host ----------------
static Proj build_proj_host() {
    const double fx = 286.2057, sk = 0.0, cxx = 162.6306;
    const double fy = 286.7852, cyy = 121.0245;
    const double w = IMG_W, h = IMG_H;
    const double nc = 0.1, fc = 10.0;
    double q  = -(fc + nc) / (fc - nc);
    double qn = -2.0 * fc * nc / (fc - nc);
    double m[4][4] = {
        {2.0 * fx / w, -2.0 * sk / w, (-2.0 * cxx + w) / w, 0.0},
        {0.0, -2.0 * fy / h, (-2.0 * cyy + h) / h, 0.0},
        {0.0, 0.0, q, qn},
        {0.0, 0.0, -1.0, 0.0}
    };
    for (int k = 0; k < 4; k++) m[1][k] *= -1.0;
    Proj P;
    for (int j = 0; j < 4; j++)
        for (int k = 0; k < 4; k++)
            P.m[4 * j + k] = (float)m[j][k];
    return P;
}

extern "C" void kernel_launch(void* const* d_in, const int* in_sizes, int n_in,
                              void* d_out, int out_size) {
    // Robust input dispatch by element count (all three are distinct):
    //   vertices: 1*12288*3 = 36864 (f32), faces: 1*4096*3 = 12288 (i32), poses: 16 (f32)
    const float* verts = nullptr;
    const int*   faces = nullptr;
    const float* pose  = nullptr;
    for (int i = 0; i < n_in; i++) {
        if (in_sizes[i] == NV * 3)       verts = (const float*)d_in[i];
        else if (in_sizes[i] == NF * 3)  faces = (const int*)d_in[i];
        else if (in_sizes[i] == 16)      pose  = (const float*)d_in[i];
    }
    float* out = (float*)d_out;                   // (1, 240, 320, 11)
    (void)out_size;

    Proj P = build_proj_host();

    k_zero_vn<<<(NV * 3 + 255) / 256, 256>>>();
    k_facenorm<<<(NF + 127) / 128, 128>>>(verts, faces);
    k_vertex<<<(NV + 255) / 256, 256>>>(verts, pose, P);
    k_facesetup<<<(NF + 127) / 128, 128>>>(faces);
    dim3 grid(IMG_W / TSZ, IMG_H / TSZ);
    dim3 blk(TSZ, TSZ);
    k_raster<<<grid, blk>>>(out);
}

// round 10
// speedup vs baseline: 2.6674x; 2.6674x over previous
#include <cuda_runtime.h>
#include <math.h>
#include <stdint.h>

#define IMG_H 240
#define IMG_W 320
#define NV 12288
#define NF 4096
#define NCH 11
#define TSZ 16
#define CHF 128   // faces per smem chunk

// ---------------- device scratch (no allocations allowed) ----------------
__device__ float g_vn[NV * 3];                 // vertex normal accumulators
__device__ float g_px[NV], g_py[NV], g_pz[NV]; // screen coords + ndc z
__device__ float g_iw[NV], g_wcl[NV];          // inv_w and clip w
__device__ float g_vcol[NV * NCH];             // per-vertex 11-ch color

struct __align__(16) FaceRec {
    float bx, by, cx, cy;
    float d0x, d0y, d1x, d1y;    // d0=(cy-by, cx-bx), d1=(ay-cy, ax-cx)
    float inv_area, z0, z1, z2;
    float iw0, iw1, iw2, pad;
};
struct __align__(16) FaceBB { float x0, x1, y0, y1; };

__device__ FaceRec g_face[NF];
__device__ FaceBB  g_bb[NF];

struct Proj { float m[16]; };   // proj matrix (numpy layout, pre-transpose)

// ---------------- kernels ----------------
__global__ void k_zero_vn() {
    int i = blockIdx.x * blockDim.x + threadIdx.x;
    if (i < NV * 3) g_vn[i] = 0.0f;
}

__global__ void k_facenorm(const float* __restrict__ verts,
                           const int* __restrict__ faces) {
    int f = blockIdx.x * blockDim.x + threadIdx.x;
    if (f >= NF) return;
    int i0 = faces[3 * f + 0], i1 = faces[3 * f + 1], i2 = faces[3 * f + 2];
    float ax = verts[3 * i0], ay = verts[3 * i0 + 1], az = verts[3 * i0 + 2];
    float bx = verts[3 * i1], by = verts[3 * i1 + 1], bz = verts[3 * i1 + 2];
    float cx = verts[3 * i2], cy = verts[3 * i2 + 1], cz = verts[3 * i2 + 2];
    float e1x = bx - ax, e1y = by - ay, e1z = bz - az;
    float e2x = cx - ax, e2y = cy - ay, e2z = cz - az;
    float nx = e1y * e2z - e1z * e2y;
    float ny = e1z * e2x - e1x * e2z;
    float nz = e1x * e2y - e1y * e2x;
    float nrm = sqrtf(nx * nx + ny * ny + nz * nz);
    nrm = fmaxf(nrm, 1e-12f);
    nx /= nrm; ny /= nrm; nz /= nrm;
    atomicAdd(&g_vn[3 * i0 + 0], nx); atomicAdd(&g_vn[3 * i0 + 1], ny); atomicAdd(&g_vn[3 * i0 + 2], nz);
    atomicAdd(&g_vn[3 * i1 + 0], nx); atomicAdd(&g_vn[3 * i1 + 1], ny); atomicAdd(&g_vn[3 * i1 + 2], nz);
    atomicAdd(&g_vn[3 * i2 + 0], nx); atomicAdd(&g_vn[3 * i2 + 1], ny); atomicAdd(&g_vn[3 * i2 + 2], nz);
}

__global__ void k_vertex(const float* __restrict__ verts,
                         const float* __restrict__ pose, Proj P) {
    int v = blockIdx.x * blockDim.x + threadIdx.x;
    if (v >= NV) return;
    float x = verts[3 * v], y = verts[3 * v + 1], z = verts[3 * v + 2];
    float p[16];
    #pragma unroll
    for (int i = 0; i < 16; i++) p[i] = pose[i];

    // vert_3d = pose_rot @ v + t
    float wx = p[0] * x + p[1] * y + p[2]  * z + p[3];
    float wy = p[4] * x + p[5] * y + p[6]  * z + p[7];
    float wz = p[8] * x + p[9] * y + p[10] * z + p[11];
    // cam = cam_pose @ [v,1];  cam_pose rows: (row0, -row1, -row2, row3)
    float cam[4];
    cam[0] = wx;
    cam[1] = -wy;
    cam[2] = -wz;
    cam[3] = p[12] * x + p[13] * y + p[14] * z + p[15];
    float clip[4];
    #pragma unroll
    for (int j = 0; j < 4; j++) {
        clip[j] = P.m[4 * j + 0] * cam[0] + P.m[4 * j + 1] * cam[1]
                + P.m[4 * j + 2] * cam[2] + P.m[4 * j + 3] * cam[3];
    }
    float wc = clip[3];
    float denw = (fabsf(wc) > 1e-9f) ? wc : 1e-9f;
    float iw = 1.0f / denw;
    float n0 = clip[0] * iw, n1 = clip[1] * iw, n2 = clip[2] * iw;
    g_px[v]  = (n0 + 1.0f) * 0.5f * (float)IMG_W;
    g_py[v]  = (1.0f - n1) * 0.5f * (float)IMG_H;
    g_pz[v]  = n2;
    g_iw[v]  = iw;
    g_wcl[v] = wc;

    // normalize accumulated vertex normal
    float vx = g_vn[3 * v], vy = g_vn[3 * v + 1], vz = g_vn[3 * v + 2];
    float nn = sqrtf(vx * vx + vy * vy + vz * vz);
    nn = fmaxf(nn, 1e-12f);
    vx /= nn; vy /= nn; vz /= nn;

    float* col = &g_vcol[v * NCH];
    col[0] = 1.0f;
    col[1] = wx; col[2] = wy; col[3] = wz;
    col[4] = vx; col[5] = vy; col[6] = vz;
    col[7] = x;  col[8] = y;  col[9] = z; col[10] = 1.0f;
}

__global__ void k_facesetup(const int* __restrict__ faces) {
    int f = blockIdx.x * blockDim.x + threadIdx.x;
    if (f >= NF) return;
    int i0 = faces[3 * f + 0], i1 = faces[3 * f + 1], i2 = faces[3 * f + 2];
    float ax = g_px[i0], ay = g_py[i0];
    float bx = g_px[i1], by = g_py[i1];
    float cx = g_px[i2], cy = g_py[i2];
    bool wok = (g_wcl[i0] > 1e-6f) && (g_wcl[i1] > 1e-6f) && (g_wcl[i2] > 1e-6f);
    float area = (bx - ax) * (cy - ay) - (by - ay) * (cx - ax);
    bool areaok = fabsf(area) > 1e-12f;
    float inv_area = 1.0f / (areaok ? area : 1e-12f);
    bool valid = areaok && wok;

    FaceRec r;
    r.bx = bx; r.by = by; r.cx = cx; r.cy = cy;
    r.d0x = cy - by; r.d0y = cx - bx;
    r.d1x = ay - cy; r.d1y = ax - cx;
    r.inv_area = valid ? inv_area : 0.0f;
    r.z0 = valid ? g_pz[i0] : 3e9f;
    r.z1 = valid ? g_pz[i1] : 3e9f;
    r.z2 = valid ? g_pz[i2] : 3e9f;
    r.iw0 = g_iw[i0]; r.iw1 = g_iw[i1]; r.iw2 = g_iw[i2];
    r.pad = 0.0f;
    g_face[f] = r;

    // Reference's e0 = -wA, e1 = -wB, e2 = 2 - wC (true barycentrics w).
    // Drawn region = triangle reflected through C: {C, 2C-A, 2C-B}.
    FaceBB bb;
    if (valid) {
        float rax = 2.0f * cx - ax, ray = 2.0f * cy - ay;   // 2C - A
        float rbx = 2.0f * cx - bx, rby = 2.0f * cy - by;   // 2C - B
        bb.x0 = fminf(cx, fminf(rax, rbx)) - 0.5f;
        bb.x1 = fmaxf(cx, fmaxf(rax, rbx)) + 0.5f;
        bb.y0 = fminf(cy, fminf(ray, rby)) - 0.5f;
        bb.y1 = fmaxf(cy, fmaxf(ray, rby)) + 0.5f;
    } else {
        bb.x0 = 1e30f; bb.x1 = -1e30f; bb.y0 = 1e30f; bb.y1 = -1e30f;
    }
    g_bb[f] = bb;
}

__global__ __launch_bounds__(TSZ * TSZ) void k_raster(float* __restrict__ out,
                                                      const int* __restrict__ faces) {
    __shared__ FaceRec sf[CHF];
    __shared__ FaceBB  sb[CHF];

    int tx = threadIdx.x, ty = threadIdx.y;
    int x = blockIdx.x * TSZ + tx;
    int y = blockIdx.y * TSZ + ty;
    float X = (float)x + 0.5f, Y = (float)y + 0.5f;
    int tid = ty * TSZ + tx;
    int lane = tid & 31;
    int warp = tid >> 5;          // warp covers rows {2*warp, 2*warp+1} of the tile

    float tX0 = (float)(blockIdx.x * TSZ) + 0.5f, tX1 = tX0 + (float)(TSZ - 1);
    float wY0 = (float)(blockIdx.y * TSZ + warp * 2) + 0.5f;
    float wY1 = wY0 + 1.0f;

    float best = 1e9f;
    int bf = -1;

    for (int base = 0; base < NF; base += CHF) {
        const float4* src = (const float4*)&g_face[base];
        float4* dst = (float4*)sf;
        #pragma unroll
        for (int i = 0; i < (CHF * 4) / (TSZ * TSZ); i++)
            dst[tid + i * TSZ * TSZ] = src[tid + i * TSZ * TSZ];
        if (tid < CHF) ((float4*)sb)[tid] = ((const float4*)&g_bb[base])[tid];
        __syncthreads();

        #pragma unroll
        for (int sub = 0; sub < CHF; sub += 32) {
            FaceBB bb = sb[sub + lane];
            bool hit = !(bb.x1 < tX0 || bb.x0 > tX1 || bb.y1 < wY0 || bb.y0 > wY1);
            unsigned m = __ballot_sync(0xffffffffu, hit);
            while (m) {
                int j = sub + (__ffs(m) - 1);
                m &= m - 1;
                const FaceRec f = sf[j];   // warp-broadcast LDS
                float e0 = ((X - f.bx) * f.d0x - (Y - f.by) * f.d0y) * f.inv_area;
                float e1 = ((X - f.cx) * f.d1x - (Y - f.cy) * f.d1y) * f.inv_area;
                float e2 = 1.0f - e0 - e1;
                float depth = e0 * f.z0 + e1 * f.z1 + e2 * f.z2;
                bool inside = (e0 >= 0.0f) & (e1 >= 0.0f) & (e2 >= 0.0f)
                            & (depth >= -1.0f) & (depth <= 1.0f);
                if (inside && depth < best) { best = depth; bf = base + j; }
            }
        }
        __syncthreads();
    }

    float col[NCH];
    if (bf >= 0) {
        FaceRec f = g_face[bf];
        float e0 = ((X - f.bx) * f.d0x - (Y - f.by) * f.d0y) * f.inv_area;
        float e1 = ((X - f.cx) * f.d1x - (Y - f.cy) * f.d1y) * f.inv_area;
        float e2 = 1.0f - e0 - e1;
        float p0 = e0 * f.iw0, p1 = e1 * f.iw1, p2 = e2 * f.iw2;
        float den = p0 + p1 + p2;
        den = (fabsf(den) > 1e-12f) ? den : 1e-12f;
        float w0 = p0 / den, w1 = p1 / den, w2 = p2 / den;
        int i0 = faces[3 * bf + 0], i1 = faces[3 * bf + 1], i2 = faces[3 * bf + 2];
        const float* c0 = &g_vcol[i0 * NCH];
        const float* c1 = &g_vcol[i1 * NCH];
        const float* c2 = &g_vcol[i2 * NCH];
        #pragma unroll
        for (int c = 0; c < NCH; c++)
            col[c] = w0 * c0[c] + w1 * c1[c] + w2 * c2[c];
    } else {
        #pragma unroll
        for (int c = 0; c < NCH; c++) col[c] = 0.0f;
    }
    float* o = out + ((size_t)y * IMG_W + x) * NCH;
    #pragma unroll
    for (int c = 0; c < NCH; c++) o[c] = col[c];
}

// ---------------- host ----------------
static Proj build_proj_host() {
    const double fx = 286.2057, sk = 0.0, cxx = 162.6306;
    const double fy = 286.7852, cyy = 121.0245;
    const double w = IMG_W, h = IMG_H;
    const double nc = 0.1, fc = 10.0;
    double q  = -(fc + nc) / (fc - nc);
    double qn = -2.0 * fc * nc / (fc - nc);
    double m[4][4] = {
        {2.0 * fx / w, -2.0 * sk / w, (-2.0 * cxx + w) / w, 0.0},
        {0.0, -2.0 * fy / h, (-2.0 * cyy + h) / h, 0.0},
        {0.0, 0.0, q, qn},
        {0.0, 0.0, -1.0, 0.0}
    };
    for (int k = 0; k < 4; k++) m[1][k] *= -1.0;
    Proj P;
    for (int j = 0; j < 4; j++)
        for (int k = 0; k < 4; k++)
            P.m[4 * j + k] = (float)m[j][k];
    return P;
}

extern "C" void kernel_launch(void* const* d_in, const int* in_sizes, int n_in,
                              void* d_out, int out_size) {
    const float* verts = nullptr;
    const int*   faces = nullptr;
    const float* pose  = nullptr;
    for (int i = 0; i < n_in; i++) {
        if (in_sizes[i] == NV * 3)       verts = (const float*)d_in[i];
        else if (in_sizes[i] == NF * 3)  faces = (const int*)d_in[i];
        else if (in_sizes[i] == 16)      pose  = (const float*)d_in[i];
    }
    float* out = (float*)d_out;                   // (1, 240, 320, 11)
    (void)out_size;

    Proj P = build_proj_host();

    k_zero_vn<<<(NV * 3 + 255) / 256, 256>>>();
    k_facenorm<<<(NF + 127) / 128, 128>>>(verts, faces);
    k_vertex<<<(NV + 255) / 256, 256>>>(verts, pose, P);
    k_facesetup<<<(NF + 127) / 128, 128>>>(faces);
    dim3 grid(IMG_W / TSZ, IMG_H / TSZ);
    dim3 blk(TSZ, TSZ);
    k_raster<<<grid, blk>>>(out, faces);
}

// round 11
// speedup vs baseline: 2.7036x; 1.0136x over previous
#include <cuda_runtime.h>
#include <math.h>
#include <stdint.h>

#define IMG_H 240
#define IMG_W 320
#define NV 12288
#define NF 4096
#define NCH 11
#define TSZ 16
#define CHF 128   // faces per smem chunk

// ---------------- device scratch (no allocations allowed) ----------------
__device__ float g_vn[NV * 3];                 // vertex normal accumulators
__device__ float g_px[NV], g_py[NV], g_pz[NV]; // screen coords + ndc z
__device__ float g_iw[NV], g_wcl[NV];          // inv_w and clip w
__device__ float g_vcol[NV * NCH];             // per-vertex 11-ch color

struct __align__(16) FaceRec {
    float bx, by, cx, cy;
    float d0x, d0y, d1x, d1y;    // d0=(cy-by, cx-bx), d1=(ay-cy, ax-cx)
    float inv_area, z0, z1, z2;
    float iw0, iw1, iw2, pad;
};
struct __align__(16) FaceBB { float x0, x1, y0, y1; };

__device__ FaceRec g_face[NF];
__device__ FaceBB  g_bb[NF];

struct Proj { float m[16]; };   // proj matrix (numpy layout, pre-transpose)

// ---------------- kernels ----------------
__global__ void k_zero_vn() {
    int i = blockIdx.x * blockDim.x + threadIdx.x;
    if (i < NV * 3) g_vn[i] = 0.0f;
}

__global__ void k_facenorm(const float* __restrict__ verts,
                           const int* __restrict__ faces) {
    int f = blockIdx.x * blockDim.x + threadIdx.x;
    if (f >= NF) return;
    int i0 = faces[3 * f + 0], i1 = faces[3 * f + 1], i2 = faces[3 * f + 2];
    float ax = verts[3 * i0], ay = verts[3 * i0 + 1], az = verts[3 * i0 + 2];
    float bx = verts[3 * i1], by = verts[3 * i1 + 1], bz = verts[3 * i1 + 2];
    float cx = verts[3 * i2], cy = verts[3 * i2 + 1], cz = verts[3 * i2 + 2];
    float e1x = bx - ax, e1y = by - ay, e1z = bz - az;
    float e2x = cx - ax, e2y = cy - ay, e2z = cz - az;
    float nx = e1y * e2z - e1z * e2y;
    float ny = e1z * e2x - e1x * e2z;
    float nz = e1x * e2y - e1y * e2x;
    float nrm = sqrtf(nx * nx + ny * ny + nz * nz);
    nrm = fmaxf(nrm, 1e-12f);
    nx /= nrm; ny /= nrm; nz /= nrm;
    atomicAdd(&g_vn[3 * i0 + 0], nx); atomicAdd(&g_vn[3 * i0 + 1], ny); atomicAdd(&g_vn[3 * i0 + 2], nz);
    atomicAdd(&g_vn[3 * i1 + 0], nx); atomicAdd(&g_vn[3 * i1 + 1], ny); atomicAdd(&g_vn[3 * i1 + 2], nz);
    atomicAdd(&g_vn[3 * i2 + 0], nx); atomicAdd(&g_vn[3 * i2 + 1], ny); atomicAdd(&g_vn[3 * i2 + 2], nz);
}

__global__ void k_vertex(const float* __restrict__ verts,
                         const float* __restrict__ pose, Proj P) {
    int v = blockIdx.x * blockDim.x + threadIdx.x;
    if (v >= NV) return;
    float x = verts[3 * v], y = verts[3 * v + 1], z = verts[3 * v + 2];
    float p[16];
    #pragma unroll
    for (int i = 0; i < 16; i++) p[i] = pose[i];

    // vert_3d = pose_rot @ v + t
    float wx = p[0] * x + p[1] * y + p[2]  * z + p[3];
    float wy = p[4] * x + p[5] * y + p[6]  * z + p[7];
    float wz = p[8] * x + p[9] * y + p[10] * z + p[11];
    // cam = cam_pose @ [v,1];  cam_pose rows: (row0, -row1, -row2, row3)
    float cam[4];
    cam[0] = wx;
    cam[1] = -wy;
    cam[2] = -wz;
    cam[3] = p[12] * x + p[13] * y + p[14] * z + p[15];
    float clip[4];
    #pragma unroll
    for (int j = 0; j < 4; j++) {
        clip[j] = P.m[4 * j + 0] * cam[0] + P.m[4 * j + 1] * cam[1]
                + P.m[4 * j + 2] * cam[2] + P.m[4 * j + 3] * cam[3];
    }
    float wc = clip[3];
    float denw = (fabsf(wc) > 1e-9f) ? wc : 1e-9f;
    float iw = 1.0f / denw;
    float n0 = clip[0] * iw, n1 = clip[1] * iw, n2 = clip[2] * iw;
    g_px[v]  = (n0 + 1.0f) * 0.5f * (float)IMG_W;
    g_py[v]  = (1.0f - n1) * 0.5f * (float)IMG_H;
    g_pz[v]  = n2;
    g_iw[v]  = iw;
    g_wcl[v] = wc;

    // normalize accumulated vertex normal
    float vx = g_vn[3 * v], vy = g_vn[3 * v + 1], vz = g_vn[3 * v + 2];
    float nn = sqrtf(vx * vx + vy * vy + vz * vz);
    nn = fmaxf(nn, 1e-12f);
    vx /= nn; vy /= nn; vz /= nn;

    float* col = &g_vcol[v * NCH];
    col[0] = 1.0f;
    col[1] = wx; col[2] = wy; col[3] = wz;
    col[4] = vx; col[5] = vy; col[6] = vz;
    col[7] = x;  col[8] = y;  col[9] = z; col[10] = 1.0f;
}

__global__ void k_facesetup(const int* __restrict__ faces) {
    int f = blockIdx.x * blockDim.x + threadIdx.x;
    if (f >= NF) return;
    int i0 = faces[3 * f + 0], i1 = faces[3 * f + 1], i2 = faces[3 * f + 2];
    float ax = g_px[i0], ay = g_py[i0];
    float bx = g_px[i1], by = g_py[i1];
    float cx = g_px[i2], cy = g_py[i2];
    bool wok = (g_wcl[i0] > 1e-6f) && (g_wcl[i1] > 1e-6f) && (g_wcl[i2] > 1e-6f);
    float area = (bx - ax) * (cy - ay) - (by - ay) * (cx - ax);
    bool areaok = fabsf(area) > 1e-12f;
    float inv_area = 1.0f / (areaok ? area : 1e-12f);
    bool valid = areaok && wok;

    FaceRec r;
    r.bx = bx; r.by = by; r.cx = cx; r.cy = cy;
    r.d0x = cy - by; r.d0y = cx - bx;
    r.d1x = ay - cy; r.d1y = ax - cx;
    r.inv_area = valid ? inv_area : 0.0f;
    r.z0 = valid ? g_pz[i0] : 3e9f;
    r.z1 = valid ? g_pz[i1] : 3e9f;
    r.z2 = valid ? g_pz[i2] : 3e9f;
    r.iw0 = g_iw[i0]; r.iw1 = g_iw[i1]; r.iw2 = g_iw[i2];
    r.pad = 0.0f;
    g_face[f] = r;

    // Reference's e0 = -wA, e1 = -wB, e2 = 2 - wC (true barycentrics w).
    // Drawn region = triangle reflected through C: {C, 2C-A, 2C-B}.
    FaceBB bb;
    if (valid) {
        float rax = 2.0f * cx - ax, ray = 2.0f * cy - ay;   // 2C - A
        float rbx = 2.0f * cx - bx, rby = 2.0f * cy - by;   // 2C - B
        bb.x0 = fminf(cx, fminf(rax, rbx)) - 0.5f;
        bb.x1 = fmaxf(cx, fmaxf(rax, rbx)) + 0.5f;
        bb.y0 = fminf(cy, fminf(ray, rby)) - 0.5f;
        bb.y1 = fmaxf(cy, fmaxf(ray, rby)) + 0.5f;
    } else {
        bb.x0 = 1e30f; bb.x1 = -1e30f; bb.y0 = 1e30f; bb.y1 = -1e30f;
    }
    g_bb[f] = bb;
}

__global__ __launch_bounds__(TSZ * TSZ) void k_raster(float* __restrict__ out,
                                                      const int* __restrict__ faces) {
    __shared__ FaceRec sf[CHF];
    __shared__ FaceBB  sb[CHF];

    int tx = threadIdx.x, ty = threadIdx.y;
    int x = blockIdx.x * TSZ + tx;
    int y = blockIdx.y * TSZ + ty;
    float X = (float)x + 0.5f, Y = (float)y + 0.5f;
    int tid = ty * TSZ + tx;
    int lane = tid & 31;
    int warp = tid >> 5;          // warp covers rows {2*warp, 2*warp+1} of the tile

    float tX0 = (float)(blockIdx.x * TSZ) + 0.5f, tX1 = tX0 + (float)(TSZ - 1);
    float wY0 = (float)(blockIdx.y * TSZ + warp * 2) + 0.5f;
    float wY1 = wY0 + 1.0f;

    float best = 1e9f;
    int bf = -1;

    for (int base = 0; base < NF; base += CHF) {
        const float4* src = (const float4*)&g_face[base];
        float4* dst = (float4*)sf;
        #pragma unroll
        for (int i = 0; i < (CHF * 4) / (TSZ * TSZ); i++)
            dst[tid + i * TSZ * TSZ] = src[tid + i * TSZ * TSZ];
        if (tid < CHF) ((float4*)sb)[tid] = ((const float4*)&g_bb[base])[tid];
        __syncthreads();

        #pragma unroll
        for (int sub = 0; sub < CHF; sub += 32) {
            FaceBB bb = sb[sub + lane];
            bool hit = !(bb.x1 < tX0 || bb.x0 > tX1 || bb.y1 < wY0 || bb.y0 > wY1);
            unsigned m = __ballot_sync(0xffffffffu, hit);
            while (m) {
                int j = sub + (__ffs(m) - 1);
                m &= m - 1;
                const FaceRec f = sf[j];   // warp-broadcast LDS
                float e0 = ((X - f.bx) * f.d0x - (Y - f.by) * f.d0y) * f.inv_area;
                float e1 = ((X - f.cx) * f.d1x - (Y - f.cy) * f.d1y) * f.inv_area;
                float e2 = 1.0f - e0 - e1;
                float depth = e0 * f.z0 + e1 * f.z1 + e2 * f.z2;
                bool inside = (e0 >= 0.0f) & (e1 >= 0.0f) & (e2 >= 0.0f)
                            & (depth >= -1.0f) & (depth <= 1.0f);
                if (inside && depth < best) { best = depth; bf = base + j; }
            }
        }
        __syncthreads();
    }

    float col[NCH];
    if (bf >= 0) {
        FaceRec f = g_face[bf];
        float e0 = ((X - f.bx) * f.d0x - (Y - f.by) * f.d0y) * f.inv_area;
        float e1 = ((X - f.cx) * f.d1x - (Y - f.cy) * f.d1y) * f.inv_area;
        float e2 = 1.0f - e0 - e1;
        float p0 = e0 * f.iw0, p1 = e1 * f.iw1, p2 = e2 * f.iw2;
        float den = p0 + p1 + p2;
        den = (fabsf(den) > 1e-12f) ? den : 1e-12f;
        float w0 = p0 / den, w1 = p1 / den, w2 = p2 / den;
        int i0 = faces[3 * bf + 0], i1 = faces[3 * bf + 1], i2 = faces[3 * bf + 2];
        const float* c0 = &g_vcol[i0 * NCH];
        const float* c1 = &g_vcol[i1 * NCH];
        const float* c2 = &g_vcol[i2 * NCH];
        #pragma unroll
        for (int c = 0; c < NCH; c++)
            col[c] = w0 * c0[c] + w1 * c1[c] + w2 * c2[c];
    } else {
        #pragma unroll
        for (int c = 0; c < NCH; c++) col[c] = 0.0f;
    }
    float* o = out + ((size_t)y * IMG_W + x) * NCH;
    #pragma unroll
    for (int c = 0; c < NCH; c++) o[c] = col[c];
}

// ---------------- host ----------------
static Proj build_proj_host() {
    const double fx = 286.2057, sk = 0.0, cxx = 162.6306;
    const double fy = 286.7852, cyy = 121.0245;
    const double w = IMG_W, h = IMG_H;
    const double nc = 0.1, fc = 10.0;
    double q  = -(fc + nc) / (fc - nc);
    double qn = -2.0 * fc * nc / (fc - nc);
    double m[4][4] = {
        {2.0 * fx / w, -2.0 * sk / w, (-2.0 * cxx + w) / w, 0.0},
        {0.0, -2.0 * fy / h, (-2.0 * cyy + h) / h, 0.0},
        {0.0, 0.0, q, qn},
        {0.0, 0.0, -1.0, 0.0}
    };
    for (int k = 0; k < 4; k++) m[1][k] *= -1.0;
    Proj P;
    for (int j = 0; j < 4; j++)
        for (int k = 0; k < 4; k++)
            P.m[4 * j + k] = (float)m[j][k];
    return P;
}

extern "C" void kernel_launch(void* const* d_in, const int* in_sizes, int n_in,
                              void* d_out, int out_size) {
    const float* verts = nullptr;
    const int*   faces = nullptr;
    const float* pose  = nullptr;
    for (int i = 0; i < n_in; i++) {
        if (in_sizes[i] == NV * 3)       verts = (const float*)d_in[i];
        else if (in_sizes[i] == NF * 3)  faces = (const int*)d_in[i];
        else if (in_sizes[i] == 16)      pose  = (const float*)d_in[i];
    }
    float* out = (float*)d_out;                   // (1, 240, 320, 11)
    (void)out_size;

    Proj P = build_proj_host();

    k_zero_vn<<<(NV * 3 + 255) / 256, 256>>>();
    k_facenorm<<<(NF + 127) / 128, 128>>>(verts, faces);
    k_vertex<<<(NV + 255) / 256, 256>>>(verts, pose, P);
    k_facesetup<<<(NF + 127) / 128, 128>>>(faces);
    dim3 grid(IMG_W / TSZ, IMG_H / TSZ);
    dim3 blk(TSZ, TSZ);
    k_raster<<<grid, blk>>>(out, faces);
}